// round 15
// baseline (speedup 1.0000x reference)
#include <cuda_runtime.h>
#include <cuda_bf16.h>
#include <math.h>
#include <stdint.h>

// Problem constants
#define BB 8
#define MM 4096
#define DD 1024
#define NEXP 64
#define NP 128            // NEXP * PP
#define BM (BB * MM)      // 32768 tokens
#define NSEG 8            // m-segments for xs reduction
#define SEGM (MM / NSEG)  // 512
#define LOG2E 1.4426950408889634f

static __device__ __constant__ float c_eps = 1e-12f;

// ---- scratch (device globals; no allocation allowed) ----
__device__ __align__(16) __nv_bfloat16 g_phinth[NP * DD];       // phin^T [np][d]
__device__ __align__(16) __nv_bfloat16 g_xh[(size_t)BM * DD];   // x bf16 [tok][d]
__device__ __align__(16) __nv_bfloat16 g_Eh[(size_t)BM * NP];   // E bf16 [tok][np]
__device__ __align__(16) __nv_bfloat16 g_ysh[BB * NP * DD];     // ys bf16 [b*NP+np][d]
__device__ __align__(16) __nv_bfloat16 g_xspb[(size_t)NSEG * BB * NP * DD]; // bf16 partial slot inputs
__device__ float g_rinv[BM];              // per-token (1/TEMP)/max(||x||,eps)
__device__ float g_part[256 * NP];        // per-mtile column partial sums
__device__ float g_rsinv[BM];             // 1/rowsum (combine denominators)

// ============================ helpers =====================================
__device__ __forceinline__ uint32_t smem_u32(const void* p) {
    uint32_t a;
    asm("{ .reg .u64 t; cvta.to.shared.u64 t, %1; cvt.u32.u64 %0, t; }"
        : "=r"(a) : "l"(p));
    return a;
}
__device__ __forceinline__ void cp_async16(uint32_t saddr, const void* gptr) {
    asm volatile("cp.async.cg.shared.global [%0], [%1], 16;"
                 :: "r"(saddr), "l"(gptr));
}
#define CP_COMMIT() asm volatile("cp.async.commit_group;" ::: "memory")
#define CP_WAIT1()  asm volatile("cp.async.wait_group 1;" ::: "memory")
__device__ __forceinline__ void ldsm_x4(uint32_t& r0, uint32_t& r1, uint32_t& r2,
                                        uint32_t& r3, uint32_t a) {
    asm volatile("ldmatrix.sync.aligned.m8n8.x4.shared.b16 {%0,%1,%2,%3}, [%4];"
                 : "=r"(r0), "=r"(r1), "=r"(r2), "=r"(r3) : "r"(a));
}
__device__ __forceinline__ void ldsm_x4t(uint32_t& r0, uint32_t& r1, uint32_t& r2,
                                         uint32_t& r3, uint32_t a) {
    asm volatile("ldmatrix.sync.aligned.m8n8.x4.trans.shared.b16 {%0,%1,%2,%3}, [%4];"
                 : "=r"(r0), "=r"(r1), "=r"(r2), "=r"(r3) : "r"(a));
}
__device__ __forceinline__ void mma_bf16(float* d, const uint32_t* a, const uint32_t* b) {
    asm volatile(
        "mma.sync.aligned.m16n8k16.row.col.f32.bf16.bf16.f32 "
        "{%0,%1,%2,%3}, {%4,%5,%6,%7}, {%8,%9}, {%0,%1,%2,%3};"
        : "+f"(d[0]), "+f"(d[1]), "+f"(d[2]), "+f"(d[3])
        : "r"(a[0]), "r"(a[1]), "r"(a[2]), "r"(a[3]), "r"(b[0]), "r"(b[1]));
}
__device__ __forceinline__ float ex2f(float x) {
    float r;
    asm("ex2.approx.f32 %0, %1;" : "=f"(r) : "f"(x));
    return r;
}
__device__ __forceinline__ float warpReduceSum(float v) {
    v += __shfl_down_sync(0xffffffffu, v, 16);
    v += __shfl_down_sync(0xffffffffu, v, 8);
    v += __shfl_down_sync(0xffffffffu, v, 4);
    v += __shfl_down_sync(0xffffffffu, v, 2);
    v += __shfl_down_sync(0xffffffffu, v, 1);
    return v;
}

// ===========================================================================
// K1: phin^T bf16
__global__ void k_phinorm(const float* __restrict__ phi, const float* __restrict__ scale) {
    int np = blockIdx.x;
    int t = threadIdx.x;
    float s = 0.f;
    for (int d = t; d < DD; d += 256) {
        float v = phi[d * NP + np];
        s += v * v;
    }
    __shared__ float red[8];
    s = warpReduceSum(s);
    if ((t & 31) == 0) red[t >> 5] = s;
    __syncthreads();
    if (t < 32) {
        float v = (t < 8) ? red[t] : 0.f;
        v = warpReduceSum(v);
        if (t == 0) red[0] = scale[0] / fmaxf(sqrtf(v), c_eps);
    }
    __syncthreads();
    float rn = red[0];
    for (int d = t; d < DD; d += 256)
        g_phinth[np * DD + d] = __float2bfloat16_rn(phi[d * NP + np] * rn);
}

// K2: row norms + x -> bf16. Warp per token.
__global__ void k_rinv(const float* __restrict__ x) {
    int w = threadIdx.x >> 5;
    int lane = threadIdx.x & 31;
    int tok = blockIdx.x * 8 + w;
    const float4* xr = reinterpret_cast<const float4*>(x + (size_t)tok * DD);
    float s = 0.f;
    #pragma unroll
    for (int i = 0; i < 8; i++) {
        float4 v = xr[lane + i * 32];
        s += v.x * v.x + v.y * v.y + v.z * v.z + v.w * v.w;
        __nv_bfloat162 p0 = __halves2bfloat162(__float2bfloat16_rn(v.x), __float2bfloat16_rn(v.y));
        __nv_bfloat162 p1 = __halves2bfloat162(__float2bfloat16_rn(v.z), __float2bfloat16_rn(v.w));
        size_t off = (size_t)tok * DD + (lane + i * 32) * 4;
        *reinterpret_cast<__nv_bfloat162*>(&g_xh[off])     = p0;
        *reinterpret_cast<__nv_bfloat162*>(&g_xh[off + 2]) = p1;
    }
    s = warpReduceSum(s);
    if (lane == 0) g_rinv[tok] = 10.0f / fmaxf(sqrtf(s), c_eps);  // 1/TEMP
}

// ===========================================================================
// K3 (mma, cp.async 3-stage, k-chunk=64): E = exp2((x.phin)*rinv*log2e).
// CTA 128m x 128n, 16 chunks of 64. Fused rowsum + column partials.
#define LDA 72
#define L_AST (128 * LDA)
#define L_SST (2 * L_AST)
__global__ __launch_bounds__(256, 2) void k_logits_mma() {
    extern __shared__ __nv_bfloat16 sm_l[];
    int t = threadIdx.x, lane = t & 31, wid = t >> 5;
    int tok0 = blockIdx.x * 128;
    int wm = wid & 1, wn = wid >> 1;
    float acc[4][4][4];
    #pragma unroll
    for (int a = 0; a < 4; a++)
        #pragma unroll
        for (int n = 0; n < 4; n++)
            #pragma unroll
            for (int q = 0; q < 4; q++) acc[a][n][q] = 0.f;

    int a_row = lane & 15;
    int a_col = (lane >> 4) * 8;
    int b_row = (lane & 7) + ((lane >> 4) << 3);
    int b_col = ((lane >> 3) & 1) * 8;

    #define L_LOAD(c, s) do { \
        __nv_bfloat16* base = sm_l + (s) * L_SST; \
        _Pragma("unroll") \
        for (int i = 0; i < 4; i++) { \
            int idx = t + i * 256; \
            int row = idx >> 3, q = idx & 7; \
            size_t ga = (size_t)(tok0 + row) * DD + (c) * 64 + q * 8; \
            size_t gb = (size_t)row * DD + (c) * 64 + q * 8; \
            int so = row * LDA + q * 8; \
            cp_async16(smem_u32(base + so), &g_xh[ga]); \
            cp_async16(smem_u32(base + L_AST + so), &g_phinth[gb]); \
        } \
    } while (0)

    L_LOAD(0, 0); CP_COMMIT();
    L_LOAD(1, 1); CP_COMMIT();
    for (int c = 0; c < 16; c++) {
        CP_WAIT1();
        __syncthreads();
        if (c + 2 < 16) L_LOAD(c + 2, (c + 2) % 3);
        CP_COMMIT();
        __nv_bfloat16* sAh = sm_l + (c % 3) * L_SST;
        __nv_bfloat16* sBh = sAh + L_AST;
        #pragma unroll
        for (int ks = 0; ks < 4; ks++) {
            uint32_t ah[4][4], bh[4][2];
            #pragma unroll
            for (int a = 0; a < 4; a++) {
                int off = (wm * 64 + a * 16 + a_row) * LDA + ks * 16 + a_col;
                ldsm_x4(ah[a][0], ah[a][1], ah[a][2], ah[a][3], smem_u32(&sAh[off]));
            }
            #pragma unroll
            for (int p = 0; p < 2; p++) {
                int off = (wn * 32 + p * 16 + b_row) * LDA + ks * 16 + b_col;
                uint32_t r0, r1, r2, r3;
                ldsm_x4(r0, r1, r2, r3, smem_u32(&sBh[off]));
                bh[p * 2][0] = r0; bh[p * 2][1] = r1;
                bh[p * 2 + 1][0] = r2; bh[p * 2 + 1][1] = r3;
            }
            #pragma unroll
            for (int a = 0; a < 4; a++)
                #pragma unroll
                for (int n = 0; n < 4; n++)
                    mma_bf16(acc[a][n], ah[a], bh[n]);
        }
    }
    // epilogue: exp2, store bf16; accumulate row/col sums (fp32, pre-rounding)
    int r0 = lane >> 2, c0 = (lane & 3) * 2;
    float rsum[4][2];
    float csum[4][2];
    #pragma unroll
    for (int a = 0; a < 4; a++) { rsum[a][0] = 0.f; rsum[a][1] = 0.f; }
    #pragma unroll
    for (int n = 0; n < 4; n++) { csum[n][0] = 0.f; csum[n][1] = 0.f; }
    __syncthreads();
    #pragma unroll
    for (int a = 0; a < 4; a++) {
        int row = tok0 + wm * 64 + a * 16 + r0;
        float rv0 = g_rinv[row] * LOG2E;
        float rv1 = g_rinv[row + 8] * LOG2E;
        #pragma unroll
        for (int n = 0; n < 4; n++) {
            int col = wn * 32 + n * 8 + c0;
            float e0 = ex2f(acc[a][n][0] * rv0), e1 = ex2f(acc[a][n][1] * rv0);
            float e2 = ex2f(acc[a][n][2] * rv1), e3 = ex2f(acc[a][n][3] * rv1);
            rsum[a][0] += e0 + e1;
            rsum[a][1] += e2 + e3;
            csum[n][0] += e0 + e2;
            csum[n][1] += e1 + e3;
            *reinterpret_cast<__nv_bfloat162*>(&g_Eh[(size_t)row * NP + col]) =
                __halves2bfloat162(__float2bfloat16_rn(e0), __float2bfloat16_rn(e1));
            *reinterpret_cast<__nv_bfloat162*>(&g_Eh[(size_t)(row + 8) * NP + col]) =
                __halves2bfloat162(__float2bfloat16_rn(e2), __float2bfloat16_rn(e3));
        }
    }
    float* srow = reinterpret_cast<float*>(sm_l);   // [4 wn][128 rows]
    float* scol = srow + 4 * 128;                   // [2 wm][128 cols]
    __syncthreads();
    #pragma unroll
    for (int a = 0; a < 4; a++)
        #pragma unroll
        for (int h = 0; h < 2; h++) {
            float v = rsum[a][h];
            v += __shfl_xor_sync(0xffffffffu, v, 1);
            v += __shfl_xor_sync(0xffffffffu, v, 2);
            if ((lane & 3) == 0)
                srow[wn * 128 + wm * 64 + a * 16 + h * 8 + r0] = v;
        }
    #pragma unroll
    for (int n = 0; n < 4; n++)
        #pragma unroll
        for (int q1 = 0; q1 < 2; q1++) {
            float v = csum[n][q1];
            v += __shfl_xor_sync(0xffffffffu, v, 4);
            v += __shfl_xor_sync(0xffffffffu, v, 8);
            v += __shfl_xor_sync(0xffffffffu, v, 16);
            if (lane < 4)
                scol[wm * 128 + wn * 32 + n * 8 + lane * 2 + q1] = v;
        }
    __syncthreads();
    if (t < 128) {
        float rs = srow[t] + srow[128 + t] + srow[256 + t] + srow[384 + t];
        g_rsinv[tok0 + t] = 1.0f / rs;
        g_part[blockIdx.x * NP + t] = scol[t] + scol[128 + t];
    }
}

// ===========================================================================
// K5 (mma, cp.async 3-stage, k-chunk=64, NSEG=8 m-segments):
// xspb[seg][b][np][d] = sum_{m in seg} E[m][np]*x[m][d].  CTA 128np x 128d.
#define LDE 136
#define X_AST (64 * LDE)
#define X_SST (2 * X_AST)
__global__ __launch_bounds__(256, 2) void k_xs_mma() {
    extern __shared__ __nv_bfloat16 sm_x[];
    int t = threadIdx.x, lane = t & 31, wid = t >> 5;
    int d0 = blockIdx.x * 128;
    int b = blockIdx.y;
    int seg = blockIdx.z;
    int base = b * MM + seg * SEGM;
    int wm = wid & 1, wn = wid >> 1;
    float acc[4][4][4];
    #pragma unroll
    for (int a = 0; a < 4; a++)
        #pragma unroll
        for (int n = 0; n < 4; n++)
            #pragma unroll
            for (int q = 0; q < 4; q++) acc[a][n][q] = 0.f;

    int aA_col = ((lane >> 3) & 1) * 8;
    int aA_row = (lane & 7) + (lane >> 4) * 8;
    int aB_row = (lane & 7) + ((lane >> 3) & 1) * 8;
    int aB_col = (lane >> 4) * 8;

    #define X_LOAD(c, s) do { \
        __nv_bfloat16* bb_ = sm_x + (s) * X_SST; \
        _Pragma("unroll") \
        for (int i = 0; i < 4; i++) { \
            int idx = t + i * 256; \
            int row = idx >> 4, q = idx & 15; \
            size_t ge = (size_t)(base + (c) * 64 + row) * NP + q * 8; \
            size_t gx = (size_t)(base + (c) * 64 + row) * DD + d0 + q * 8; \
            int so = row * LDE + q * 8; \
            cp_async16(smem_u32(bb_ + so), &g_Eh[ge]); \
            cp_async16(smem_u32(bb_ + X_AST + so), &g_xh[gx]); \
        } \
    } while (0)

    X_LOAD(0, 0); CP_COMMIT();
    X_LOAD(1, 1); CP_COMMIT();
    for (int c = 0; c < SEGM / 64; c++) {
        CP_WAIT1();
        __syncthreads();
        if (c + 2 < SEGM / 64) X_LOAD(c + 2, (c + 2) % 3);
        CP_COMMIT();
        __nv_bfloat16* sEh = sm_x + (c % 3) * X_SST;
        __nv_bfloat16* sXh = sEh + X_AST;
        #pragma unroll
        for (int ks = 0; ks < 4; ks++) {
            uint32_t ah[4][4], bh[4][2];
            #pragma unroll
            for (int a = 0; a < 4; a++) {
                int npb = wm * 64 + a * 16 + aA_col;
                int off = (ks * 16 + aA_row) * LDE + npb;
                ldsm_x4t(ah[a][0], ah[a][1], ah[a][2], ah[a][3], smem_u32(&sEh[off]));
            }
            #pragma unroll
            for (int p = 0; p < 2; p++) {
                int nb = wn * 32 + p * 16 + aB_col;
                int off = (ks * 16 + aB_row) * LDE + nb;
                uint32_t r0, r1, r2, r3;
                ldsm_x4t(r0, r1, r2, r3, smem_u32(&sXh[off]));
                bh[p * 2][0] = r0; bh[p * 2][1] = r1;
                bh[p * 2 + 1][0] = r2; bh[p * 2 + 1][1] = r3;
            }
            #pragma unroll
            for (int a = 0; a < 4; a++)
                #pragma unroll
                for (int n = 0; n < 4; n++)
                    mma_bf16(acc[a][n], ah[a], bh[n]);
        }
    }
    int r0 = lane >> 2, c0 = (lane & 3) * 2;
    #pragma unroll
    for (int a = 0; a < 4; a++) {
        int np = wm * 64 + a * 16 + r0;
        #pragma unroll
        for (int n = 0; n < 4; n++) {
            int d = d0 + wn * 32 + n * 8 + c0;
            size_t o0 = (((size_t)seg * BB + b) * NP + np) * DD + d;
            size_t o1 = (((size_t)seg * BB + b) * NP + np + 8) * DD + d;
            *reinterpret_cast<__nv_bfloat162*>(&g_xspb[o0]) =
                __halves2bfloat162(__float2bfloat16_rn(acc[a][n][0]),
                                   __float2bfloat16_rn(acc[a][n][1]));
            *reinterpret_cast<__nv_bfloat162*>(&g_xspb[o1]) =
                __halves2bfloat162(__float2bfloat16_rn(acc[a][n][2]),
                                   __float2bfloat16_rn(acc[a][n][3]));
        }
    }
}

// ===========================================================================
// K6 (mma, cp.async W staging): ys[(b,p)][e] = sum_d xs*W + bias.
// K chunks of 32; W staged fp32 via cp.async (2 stages), converted from smem.
// Colsum reduce folded in (reads g_part directly); A from bf16 xspb (NSEG segs).
#define LDW 264
#define LDK 40
#define YLDWF 264                         // fp32 stage row stride (floats)
#define Y_FST (32 * YLDWF)                // floats per W stage
#define Y_WT (32 * LDW)                   // bf16 elems per W tile
#define Y_AT (16 * LDK)                   // bf16 elems per A tile
__global__ __launch_bounds__(256) void k_ys_mma(const float* __restrict__ W,
                                                const float* __restrict__ bias) {
    extern __shared__ char sm_raw_y[];
    float* sWf = reinterpret_cast<float*>(sm_raw_y);                 // 2 stages fp32
    __nv_bfloat16* sWh = reinterpret_cast<__nv_bfloat16*>(sm_raw_y + 2 * Y_FST * 4); // 2 tiles
    __nv_bfloat16* sAh = sWh + 2 * Y_WT;                             // 2 tiles
    int t = threadIdx.x, lane = t & 31, wid = t >> 5;
    int nexp = blockIdx.y;
    int e0 = blockIdx.x * 256;
    float acc[4][4];
    #pragma unroll
    for (int n = 0; n < 4; n++)
        #pragma unroll
        for (int q = 0; q < 4; q++) acc[n][q] = 0.f;

    int a_row = lane & 15;
    int a_col = (lane >> 4) * 8;
    int aB_row = (lane & 7) + ((lane >> 3) & 1) * 8;
    int aB_col = (lane >> 4) * 8;

    // folded colsum: per-thread A row state (t<128)
    int arow = t >> 3, aq = t & 7;        // row 0..15, col-group 0..7 (4 elems)
    int abb = arow >> 1, ap = arow & 1;
    float ainv = 0.f;
    if (t < 128) {
        int npi = nexp * 2 + ap;
        float cs = 0.f;
        #pragma unroll
        for (int i = 0; i < 32; i++)
            cs += g_part[(abb * 32 + i) * NP + npi];
        ainv = 1.0f / cs;
    }
    size_t abase = ((size_t)abb * NP + nexp * 2 + ap) * DD + aq * 4;

    // W stage load: 32 k-rows x 256 e = 2048 float4; 8 per thread
    #define Y_LOAD(c, s) do { \
        float* dst = sWf + (s) * Y_FST; \
        _Pragma("unroll") \
        for (int i = 0; i < 8; i++) { \
            int idx = t + i * 256; \
            int row = idx >> 6, q = idx & 63; \
            cp_async16(smem_u32(dst + row * YLDWF + q * 4), \
                       &W[((size_t)nexp * DD + (c) * 32 + row) * DD + e0 + q * 4]); \
        } \
    } while (0)

    Y_LOAD(0, 0);
    CP_COMMIT();
    Y_LOAD(1, 1);
    CP_COMMIT();
    for (int c = 0; c < 32; c++) {
        CP_WAIT1();
        __syncthreads();
        // convert W stage -> bf16 tile (each thread 4x8 floats)
        {
            const float* src = sWf + (c & 1) * Y_FST;
            __nv_bfloat16* dst = sWh + (c & 1) * Y_WT;
            #pragma unroll
            for (int i = 0; i < 4; i++) {
                int idx = t + i * 256;
                int row = idx >> 5, q = idx & 31;    // 32 rows x 32 groups of 8
                const float* sp = src + row * YLDWF + q * 8;
                float4 v0 = *reinterpret_cast<const float4*>(sp);
                float4 v1 = *reinterpret_cast<const float4*>(sp + 4);
                uint32_t hs[8];
                hs[0] = (uint32_t)__bfloat16_as_ushort(__float2bfloat16_rn(v0.x));
                hs[1] = (uint32_t)__bfloat16_as_ushort(__float2bfloat16_rn(v0.y));
                hs[2] = (uint32_t)__bfloat16_as_ushort(__float2bfloat16_rn(v0.z));
                hs[3] = (uint32_t)__bfloat16_as_ushort(__float2bfloat16_rn(v0.w));
                hs[4] = (uint32_t)__bfloat16_as_ushort(__float2bfloat16_rn(v1.x));
                hs[5] = (uint32_t)__bfloat16_as_ushort(__float2bfloat16_rn(v1.y));
                hs[6] = (uint32_t)__bfloat16_as_ushort(__float2bfloat16_rn(v1.z));
                hs[7] = (uint32_t)__bfloat16_as_ushort(__float2bfloat16_rn(v1.w));
                uint4 hi = {hs[0] | (hs[1] << 16), hs[2] | (hs[3] << 16),
                            hs[4] | (hs[5] << 16), hs[6] | (hs[7] << 16)};
                *reinterpret_cast<uint4*>(&dst[row * LDW + q * 8]) = hi;
            }
        }
        // A tile: 16 rows x 32 k, NSEG-seg bf16 sum * ainv, convert
        if (t < 128) {
            size_t off = abase + c * 32;
            float s0 = 0.f, s1 = 0.f, s2 = 0.f, s3 = 0.f;
            #pragma unroll
            for (int seg = 0; seg < NSEG; seg++) {
                uint2 pk = *reinterpret_cast<const uint2*>(
                    &g_xspb[(size_t)seg * BB * NP * DD + off]);
                __nv_bfloat162 p0 = *reinterpret_cast<const __nv_bfloat162*>(&pk.x);
                __nv_bfloat162 p1 = *reinterpret_cast<const __nv_bfloat162*>(&pk.y);
                s0 += __bfloat162float(p0.x); s1 += __bfloat162float(p0.y);
                s2 += __bfloat162float(p1.x); s3 += __bfloat162float(p1.y);
            }
            uint32_t h0 = (uint32_t)__bfloat16_as_ushort(__float2bfloat16_rn(s0 * ainv));
            uint32_t h1 = (uint32_t)__bfloat16_as_ushort(__float2bfloat16_rn(s1 * ainv));
            uint32_t h2 = (uint32_t)__bfloat16_as_ushort(__float2bfloat16_rn(s2 * ainv));
            uint32_t h3 = (uint32_t)__bfloat16_as_ushort(__float2bfloat16_rn(s3 * ainv));
            uint2 pk = {h0 | (h1 << 16), h2 | (h3 << 16)};
            *reinterpret_cast<uint2*>(&sAh[(c & 1) * Y_AT + arow * LDK + aq * 4]) = pk;
        }
        __syncthreads();
        if (c + 2 < 32) { Y_LOAD(c + 2, c & 1); }
        CP_COMMIT();
        // mma on tile (c&1)
        __nv_bfloat16* tW = sWh + (c & 1) * Y_WT;
        __nv_bfloat16* tA = sAh + (c & 1) * Y_AT;
        #pragma unroll
        for (int ks = 0; ks < 2; ks++) {
            uint32_t ah[4], bh[4][2];
            {
                int off = a_row * LDK + ks * 16 + a_col;
                ldsm_x4(ah[0], ah[1], ah[2], ah[3], smem_u32(&tA[off]));
            }
            #pragma unroll
            for (int p = 0; p < 2; p++) {
                int nb = wid * 32 + p * 16 + aB_col;
                int off = (ks * 16 + aB_row) * LDW + nb;
                uint32_t r0, r1, r2, r3;
                ldsm_x4t(r0, r1, r2, r3, smem_u32(&tW[off]));
                bh[p * 2][0] = r0; bh[p * 2][1] = r1;
                bh[p * 2 + 1][0] = r2; bh[p * 2 + 1][1] = r3;
            }
            #pragma unroll
            for (int n = 0; n < 4; n++)
                mma_bf16(acc[n], ah, bh[n]);
        }
    }
    int r0 = lane >> 2, c0 = (lane & 3) * 2;
    #pragma unroll
    for (int n = 0; n < 4; n++) {
        int e = e0 + wid * 32 + n * 8 + c0;
        float2 bv = *reinterpret_cast<const float2*>(&bias[nexp * DD + e]);
        #pragma unroll
        for (int h = 0; h < 2; h++) {
            int row = r0 + h * 8;
            int bb = row >> 1, p = row & 1;
            float v0 = acc[n][h * 2 + 0] + bv.x;
            float v1 = acc[n][h * 2 + 1] + bv.y;
            size_t o = ((size_t)bb * NP + nexp * 2 + p) * DD + e;
            *reinterpret_cast<__nv_bfloat162*>(&g_ysh[o]) =
                __halves2bfloat162(__float2bfloat16_rn(v0), __float2bfloat16_rn(v1));
        }
    }
}

// ===========================================================================
// K7 (mma, cp.async 3-stage): y[m][d] = rsinv[m]*sum_np E[m][np]*ys[np][d] + x[m][d]
#define CLDA 40
#define C_ASZ (128 * CLDA)
#define C_BSZ (32 * LDE)
#define C_SST (C_ASZ + C_BSZ)
__global__ __launch_bounds__(256) void k_combine_mma(const float* __restrict__ x,
                                                     float* __restrict__ y) {
    extern __shared__ __nv_bfloat16 sm_c[];
    int t = threadIdx.x, lane = t & 31, wid = t >> 5;
    int b = blockIdx.z;
    int tokbase = b * MM + blockIdx.x * 128;
    int d0 = blockIdx.y * 128;
    int wm = wid & 1, wn = wid >> 1;
    float acc[4][4][4];
    #pragma unroll
    for (int a = 0; a < 4; a++)
        #pragma unroll
        for (int n = 0; n < 4; n++)
            #pragma unroll
            for (int q = 0; q < 4; q++) acc[a][n][q] = 0.f;

    int a_row = lane & 15;
    int a_col = (lane >> 4) * 8;
    int aB_row = (lane & 7) + ((lane >> 3) & 1) * 8;
    int aB_col = (lane >> 4) * 8;

    #define C_LOAD(c, s) do { \
        __nv_bfloat16* base = sm_c + (s) * C_SST; \
        _Pragma("unroll") \
        for (int i = 0; i < 2; i++) { \
            int idx = t + i * 256; \
            int row = idx >> 2, q = idx & 3; \
            size_t ge = (size_t)(tokbase + row) * NP + (c) * 32 + q * 8; \
            cp_async16(smem_u32(base + row * CLDA + q * 8), &g_Eh[ge]); \
            int rowb = idx >> 4, qb = idx & 15; \
            size_t gy = ((size_t)b * NP + (c) * 32 + rowb) * DD + d0 + qb * 8; \
            cp_async16(smem_u32(base + C_ASZ + rowb * LDE + qb * 8), &g_ysh[gy]); \
        } \
    } while (0)

    C_LOAD(0, 0);
    CP_COMMIT();
    C_LOAD(1, 1);
    CP_COMMIT();
    for (int c = 0; c < 4; c++) {
        CP_WAIT1();
        __syncthreads();
        if (c + 2 < 4) C_LOAD(c + 2, (c + 2) % 3);
        CP_COMMIT();
        __nv_bfloat16* sAh = sm_c + (c % 3) * C_SST;
        __nv_bfloat16* sBh = sAh + C_ASZ;
        #pragma unroll
        for (int ks = 0; ks < 2; ks++) {
            uint32_t ah[4][4], bh[4][2];
            #pragma unroll
            for (int a = 0; a < 4; a++) {
                int off = (wm * 64 + a * 16 + a_row) * CLDA + ks * 16 + a_col;
                ldsm_x4(ah[a][0], ah[a][1], ah[a][2], ah[a][3], smem_u32(&sAh[off]));
            }
            #pragma unroll
            for (int p = 0; p < 2; p++) {
                int nb = wn * 32 + p * 16 + aB_col;
                int off = (ks * 16 + aB_row) * LDE + nb;
                uint32_t r0, r1, r2, r3;
                ldsm_x4t(r0, r1, r2, r3, smem_u32(&sBh[off]));
                bh[p * 2][0] = r0; bh[p * 2][1] = r1;
                bh[p * 2 + 1][0] = r2; bh[p * 2 + 1][1] = r3;
            }
            #pragma unroll
            for (int a = 0; a < 4; a++)
                #pragma unroll
                for (int n = 0; n < 4; n++)
                    mma_bf16(acc[a][n], ah[a], bh[n]);
        }
    }
    int r0 = lane >> 2, c0 = (lane & 3) * 2;
    #pragma unroll
    for (int a = 0; a < 4; a++) {
        int m0 = tokbase + wm * 64 + a * 16 + r0;
        float rs0 = g_rsinv[m0];
        float rs1 = g_rsinv[m0 + 8];
        #pragma unroll
        for (int n = 0; n < 4; n++) {
            int d = d0 + wn * 32 + n * 8 + c0;
            size_t i0 = (size_t)m0 * DD + d;
            size_t i1 = (size_t)(m0 + 8) * DD + d;
            float2 xv0 = *reinterpret_cast<const float2*>(&x[i0]);
            float2 xv1 = *reinterpret_cast<const float2*>(&x[i1]);
            *reinterpret_cast<float2*>(&y[i0]) =
                make_float2(acc[a][n][0] * rs0 + xv0.x, acc[a][n][1] * rs0 + xv0.y);
            *reinterpret_cast<float2*>(&y[i1]) =
                make_float2(acc[a][n][2] * rs1 + xv1.x, acc[a][n][3] * rs1 + xv1.y);
        }
    }
}

// ---------------------------------------------------------------------------
extern "C" void kernel_launch(void* const* d_in, const int* in_sizes, int n_in,
                              void* d_out, int out_size) {
    const float* x     = (const float*)d_in[0];  // [8,4096,1024]
    const float* phi   = (const float*)d_in[1];  // [1024,64,2]
    const float* scale = (const float*)d_in[2];  // [1]
    const float* W     = (const float*)d_in[3];  // [64,1024,1024]
    const float* bias  = (const float*)d_in[4];  // [64,1024]
    float* y = (float*)d_out;                    // [8,4096,1024]

    const int smem_logits  = 3 * L_SST * 2;                             // 110592
    const int smem_xs      = 3 * X_SST * 2;                             // 104448
    const int smem_ys      = 2 * Y_FST * 4 + 2 * Y_WT * 2 + 2 * Y_AT * 2; // 104448
    const int smem_combine = 3 * C_SST * 2;                             // 56832
    cudaFuncSetAttribute(k_logits_mma, cudaFuncAttributeMaxDynamicSharedMemorySize, smem_logits);
    cudaFuncSetAttribute(k_xs_mma, cudaFuncAttributeMaxDynamicSharedMemorySize, smem_xs);
    cudaFuncSetAttribute(k_ys_mma, cudaFuncAttributeMaxDynamicSharedMemorySize, smem_ys);
    cudaFuncSetAttribute(k_combine_mma, cudaFuncAttributeMaxDynamicSharedMemorySize, smem_combine);

    k_phinorm<<<NP, 256>>>(phi, scale);
    k_rinv<<<BM / 8, 256>>>(x);
    k_logits_mma<<<BM / 128, 256, smem_logits>>>();
    k_xs_mma<<<dim3(8, BB, NSEG), 256, smem_xs>>>();
    k_ys_mma<<<dim3(4, NEXP), 256, smem_ys>>>(W, bias);
    k_combine_mma<<<dim3(32, 8, BB), 256, smem_combine>>>(x, y);
}

// round 16
// speedup vs baseline: 1.0411x; 1.0411x over previous
#include <cuda_runtime.h>
#include <cuda_bf16.h>
#include <math.h>
#include <stdint.h>

// Problem constants
#define BB 8
#define MM 4096
#define DD 1024
#define NEXP 64
#define NP 128            // NEXP * PP
#define BM (BB * MM)      // 32768 tokens
#define NSEG 4            // m-segments for xs reduction
#define SEGM (MM / NSEG)  // 1024
#define LOG2E 1.4426950408889634f

static __device__ __constant__ float c_eps = 1e-12f;

// ---- scratch (device globals; no allocation allowed) ----
__device__ __align__(16) __nv_bfloat16 g_phinth[NP * DD];       // phin^T [np][d]
__device__ __align__(16) __nv_bfloat16 g_xh[(size_t)BM * DD];   // x bf16 [tok][d]
__device__ __align__(16) __nv_bfloat16 g_Eh[(size_t)BM * NP];   // E bf16 [tok][np]
__device__ __align__(16) __nv_bfloat16 g_ysh[BB * NP * DD];     // ys bf16 [b*NP+np][d]
__device__ __align__(16) __nv_bfloat16 g_xspb[(size_t)NSEG * BB * NP * DD]; // bf16 partial slot inputs
__device__ float g_rinv[BM];              // per-token (1/TEMP)/max(||x||,eps)
__device__ float g_part[256 * NP];        // per-mtile column partial sums
__device__ float g_rsinv[BM];             // 1/rowsum (combine denominators)

// ============================ helpers =====================================
__device__ __forceinline__ uint32_t smem_u32(const void* p) {
    uint32_t a;
    asm("{ .reg .u64 t; cvta.to.shared.u64 t, %1; cvt.u32.u64 %0, t; }"
        : "=r"(a) : "l"(p));
    return a;
}
__device__ __forceinline__ void cp_async16(uint32_t saddr, const void* gptr) {
    asm volatile("cp.async.cg.shared.global [%0], [%1], 16;"
                 :: "r"(saddr), "l"(gptr));
}
#define CP_COMMIT() asm volatile("cp.async.commit_group;" ::: "memory")
#define CP_WAIT1()  asm volatile("cp.async.wait_group 1;" ::: "memory")
__device__ __forceinline__ void ldsm_x4(uint32_t& r0, uint32_t& r1, uint32_t& r2,
                                        uint32_t& r3, uint32_t a) {
    asm volatile("ldmatrix.sync.aligned.m8n8.x4.shared.b16 {%0,%1,%2,%3}, [%4];"
                 : "=r"(r0), "=r"(r1), "=r"(r2), "=r"(r3) : "r"(a));
}
__device__ __forceinline__ void ldsm_x4t(uint32_t& r0, uint32_t& r1, uint32_t& r2,
                                         uint32_t& r3, uint32_t a) {
    asm volatile("ldmatrix.sync.aligned.m8n8.x4.trans.shared.b16 {%0,%1,%2,%3}, [%4];"
                 : "=r"(r0), "=r"(r1), "=r"(r2), "=r"(r3) : "r"(a));
}
__device__ __forceinline__ void mma_bf16(float* d, const uint32_t* a, const uint32_t* b) {
    asm volatile(
        "mma.sync.aligned.m16n8k16.row.col.f32.bf16.bf16.f32 "
        "{%0,%1,%2,%3}, {%4,%5,%6,%7}, {%8,%9}, {%0,%1,%2,%3};"
        : "+f"(d[0]), "+f"(d[1]), "+f"(d[2]), "+f"(d[3])
        : "r"(a[0]), "r"(a[1]), "r"(a[2]), "r"(a[3]), "r"(b[0]), "r"(b[1]));
}
__device__ __forceinline__ float ex2f(float x) {
    float r;
    asm("ex2.approx.f32 %0, %1;" : "=f"(r) : "f"(x));
    return r;
}
__device__ __forceinline__ float warpReduceSum(float v) {
    v += __shfl_down_sync(0xffffffffu, v, 16);
    v += __shfl_down_sync(0xffffffffu, v, 8);
    v += __shfl_down_sync(0xffffffffu, v, 4);
    v += __shfl_down_sync(0xffffffffu, v, 2);
    v += __shfl_down_sync(0xffffffffu, v, 1);
    return v;
}

// ===========================================================================
// K1: phin^T bf16
__global__ void k_phinorm(const float* __restrict__ phi, const float* __restrict__ scale) {
    int np = blockIdx.x;
    int t = threadIdx.x;
    float s = 0.f;
    for (int d = t; d < DD; d += 256) {
        float v = phi[d * NP + np];
        s += v * v;
    }
    __shared__ float red[8];
    s = warpReduceSum(s);
    if ((t & 31) == 0) red[t >> 5] = s;
    __syncthreads();
    if (t < 32) {
        float v = (t < 8) ? red[t] : 0.f;
        v = warpReduceSum(v);
        if (t == 0) red[0] = scale[0] / fmaxf(sqrtf(v), c_eps);
    }
    __syncthreads();
    float rn = red[0];
    for (int d = t; d < DD; d += 256)
        g_phinth[np * DD + d] = __float2bfloat16_rn(phi[d * NP + np] * rn);
}

// K2: row norms + x -> bf16. Warp per token.
__global__ void k_rinv(const float* __restrict__ x) {
    int w = threadIdx.x >> 5;
    int lane = threadIdx.x & 31;
    int tok = blockIdx.x * 8 + w;
    const float4* xr = reinterpret_cast<const float4*>(x + (size_t)tok * DD);
    float s = 0.f;
    #pragma unroll
    for (int i = 0; i < 8; i++) {
        float4 v = xr[lane + i * 32];
        s += v.x * v.x + v.y * v.y + v.z * v.z + v.w * v.w;
        __nv_bfloat162 p0 = __halves2bfloat162(__float2bfloat16_rn(v.x), __float2bfloat16_rn(v.y));
        __nv_bfloat162 p1 = __halves2bfloat162(__float2bfloat16_rn(v.z), __float2bfloat16_rn(v.w));
        size_t off = (size_t)tok * DD + (lane + i * 32) * 4;
        *reinterpret_cast<__nv_bfloat162*>(&g_xh[off])     = p0;
        *reinterpret_cast<__nv_bfloat162*>(&g_xh[off + 2]) = p1;
    }
    s = warpReduceSum(s);
    if (lane == 0) g_rinv[tok] = 10.0f / fmaxf(sqrtf(s), c_eps);  // 1/TEMP
}

// ===========================================================================
// K3 (mma, 512 threads, cp.async 3-stage, k-chunk=64):
// E = exp2((x.phin)*rinv*log2e). CTA 128m x 128n, warp tile 32x32.
#define LDA 72
#define L_AST (128 * LDA)
#define L_SST (2 * L_AST)
__global__ __launch_bounds__(512, 2) void k_logits_mma() {
    extern __shared__ __nv_bfloat16 sm_l[];
    int t = threadIdx.x, lane = t & 31, wid = t >> 5;
    int tok0 = blockIdx.x * 128;
    int wm = wid & 3, wn = wid >> 2;
    float acc[2][4][4];
    #pragma unroll
    for (int a = 0; a < 2; a++)
        #pragma unroll
        for (int n = 0; n < 4; n++)
            #pragma unroll
            for (int q = 0; q < 4; q++) acc[a][n][q] = 0.f;

    int a_row = lane & 15;
    int a_col = (lane >> 4) * 8;
    int b_row = (lane & 7) + ((lane >> 4) << 3);
    int b_col = ((lane >> 3) & 1) * 8;

    #define L_LOAD(c, s) do { \
        __nv_bfloat16* base = sm_l + (s) * L_SST; \
        _Pragma("unroll") \
        for (int i = 0; i < 2; i++) { \
            int idx = t + i * 512; \
            int row = idx >> 3, q = idx & 7; \
            size_t ga = (size_t)(tok0 + row) * DD + (c) * 64 + q * 8; \
            size_t gb = (size_t)row * DD + (c) * 64 + q * 8; \
            int so = row * LDA + q * 8; \
            cp_async16(smem_u32(base + so), &g_xh[ga]); \
            cp_async16(smem_u32(base + L_AST + so), &g_phinth[gb]); \
        } \
    } while (0)

    L_LOAD(0, 0); CP_COMMIT();
    L_LOAD(1, 1); CP_COMMIT();
    for (int c = 0; c < 16; c++) {
        CP_WAIT1();
        __syncthreads();
        if (c + 2 < 16) L_LOAD(c + 2, (c + 2) % 3);
        CP_COMMIT();
        __nv_bfloat16* sAh = sm_l + (c % 3) * L_SST;
        __nv_bfloat16* sBh = sAh + L_AST;
        #pragma unroll
        for (int ks = 0; ks < 4; ks++) {
            uint32_t ah[2][4], bh[4][2];
            #pragma unroll
            for (int a = 0; a < 2; a++) {
                int off = (wm * 32 + a * 16 + a_row) * LDA + ks * 16 + a_col;
                ldsm_x4(ah[a][0], ah[a][1], ah[a][2], ah[a][3], smem_u32(&sAh[off]));
            }
            #pragma unroll
            for (int p = 0; p < 2; p++) {
                int off = (wn * 32 + p * 16 + b_row) * LDA + ks * 16 + b_col;
                uint32_t r0, r1, r2, r3;
                ldsm_x4(r0, r1, r2, r3, smem_u32(&sBh[off]));
                bh[p * 2][0] = r0; bh[p * 2][1] = r1;
                bh[p * 2 + 1][0] = r2; bh[p * 2 + 1][1] = r3;
            }
            #pragma unroll
            for (int a = 0; a < 2; a++)
                #pragma unroll
                for (int n = 0; n < 4; n++)
                    mma_bf16(acc[a][n], ah[a], bh[n]);
        }
    }
    // epilogue: exp2, store bf16; accumulate row/col sums (fp32, pre-rounding)
    int r0 = lane >> 2, c0 = (lane & 3) * 2;
    float rsum[2][2];
    float csum[4][2];
    #pragma unroll
    for (int a = 0; a < 2; a++) { rsum[a][0] = 0.f; rsum[a][1] = 0.f; }
    #pragma unroll
    for (int n = 0; n < 4; n++) { csum[n][0] = 0.f; csum[n][1] = 0.f; }
    __syncthreads();
    #pragma unroll
    for (int a = 0; a < 2; a++) {
        int row = tok0 + wm * 32 + a * 16 + r0;
        float rv0 = g_rinv[row] * LOG2E;
        float rv1 = g_rinv[row + 8] * LOG2E;
        #pragma unroll
        for (int n = 0; n < 4; n++) {
            int col = wn * 32 + n * 8 + c0;
            float e0 = ex2f(acc[a][n][0] * rv0), e1 = ex2f(acc[a][n][1] * rv0);
            float e2 = ex2f(acc[a][n][2] * rv1), e3 = ex2f(acc[a][n][3] * rv1);
            rsum[a][0] += e0 + e1;
            rsum[a][1] += e2 + e3;
            csum[n][0] += e0 + e2;
            csum[n][1] += e1 + e3;
            *reinterpret_cast<__nv_bfloat162*>(&g_Eh[(size_t)row * NP + col]) =
                __halves2bfloat162(__float2bfloat16_rn(e0), __float2bfloat16_rn(e1));
            *reinterpret_cast<__nv_bfloat162*>(&g_Eh[(size_t)(row + 8) * NP + col]) =
                __halves2bfloat162(__float2bfloat16_rn(e2), __float2bfloat16_rn(e3));
        }
    }
    float* srow = reinterpret_cast<float*>(sm_l);   // [4 wn][128 rows]
    float* scol = srow + 4 * 128;                   // [4 wm][128 cols]
    __syncthreads();
    #pragma unroll
    for (int a = 0; a < 2; a++)
        #pragma unroll
        for (int h = 0; h < 2; h++) {
            float v = rsum[a][h];
            v += __shfl_xor_sync(0xffffffffu, v, 1);
            v += __shfl_xor_sync(0xffffffffu, v, 2);
            if ((lane & 3) == 0)
                srow[wn * 128 + wm * 32 + a * 16 + h * 8 + r0] = v;
        }
    #pragma unroll
    for (int n = 0; n < 4; n++)
        #pragma unroll
        for (int q1 = 0; q1 < 2; q1++) {
            float v = csum[n][q1];
            v += __shfl_xor_sync(0xffffffffu, v, 4);
            v += __shfl_xor_sync(0xffffffffu, v, 8);
            v += __shfl_xor_sync(0xffffffffu, v, 16);
            if (lane < 4)
                scol[wm * 128 + wn * 32 + n * 8 + lane * 2 + q1] = v;
        }
    __syncthreads();
    if (t < 128) {
        float rs = srow[t] + srow[128 + t] + srow[256 + t] + srow[384 + t];
        g_rsinv[tok0 + t] = 1.0f / rs;
        g_part[blockIdx.x * NP + t] =
            scol[t] + scol[128 + t] + scol[256 + t] + scol[384 + t];
    }
}

// ===========================================================================
// K5 (mma, 512 threads, cp.async 3-stage, k-chunk=64, NSEG=4):
// xspb[seg][b][np][d] = sum_{m in seg} E[m][np]*x[m][d]. CTA 128np x 128d, warp 32x32.
#define LDE 136
#define X_AST (64 * LDE)
#define X_SST (2 * X_AST)
__global__ __launch_bounds__(512, 2) void k_xs_mma() {
    extern __shared__ __nv_bfloat16 sm_x[];
    int t = threadIdx.x, lane = t & 31, wid = t >> 5;
    int d0 = blockIdx.x * 128;
    int b = blockIdx.y;
    int seg = blockIdx.z;
    int base = b * MM + seg * SEGM;
    int wm = wid & 3, wn = wid >> 2;
    float acc[2][4][4];
    #pragma unroll
    for (int a = 0; a < 2; a++)
        #pragma unroll
        for (int n = 0; n < 4; n++)
            #pragma unroll
            for (int q = 0; q < 4; q++) acc[a][n][q] = 0.f;

    int aA_col = ((lane >> 3) & 1) * 8;
    int aA_row = (lane & 7) + (lane >> 4) * 8;
    int aB_row = (lane & 7) + ((lane >> 3) & 1) * 8;
    int aB_col = (lane >> 4) * 8;

    #define X_LOAD(c, s) do { \
        __nv_bfloat16* bb_ = sm_x + (s) * X_SST; \
        _Pragma("unroll") \
        for (int i = 0; i < 2; i++) { \
            int idx = t + i * 512; \
            int row = idx >> 4, q = idx & 15; \
            size_t ge = (size_t)(base + (c) * 64 + row) * NP + q * 8; \
            size_t gx = (size_t)(base + (c) * 64 + row) * DD + d0 + q * 8; \
            int so = row * LDE + q * 8; \
            cp_async16(smem_u32(bb_ + so), &g_Eh[ge]); \
            cp_async16(smem_u32(bb_ + X_AST + so), &g_xh[gx]); \
        } \
    } while (0)

    X_LOAD(0, 0); CP_COMMIT();
    X_LOAD(1, 1); CP_COMMIT();
    for (int c = 0; c < SEGM / 64; c++) {
        CP_WAIT1();
        __syncthreads();
        if (c + 2 < SEGM / 64) X_LOAD(c + 2, (c + 2) % 3);
        CP_COMMIT();
        __nv_bfloat16* sEh = sm_x + (c % 3) * X_SST;
        __nv_bfloat16* sXh = sEh + X_AST;
        #pragma unroll
        for (int ks = 0; ks < 4; ks++) {
            uint32_t ah[2][4], bh[4][2];
            #pragma unroll
            for (int a = 0; a < 2; a++) {
                int npb = wm * 32 + a * 16 + aA_col;
                int off = (ks * 16 + aA_row) * LDE + npb;
                ldsm_x4t(ah[a][0], ah[a][1], ah[a][2], ah[a][3], smem_u32(&sEh[off]));
            }
            #pragma unroll
            for (int p = 0; p < 2; p++) {
                int nb = wn * 32 + p * 16 + aB_col;
                int off = (ks * 16 + aB_row) * LDE + nb;
                uint32_t r0, r1, r2, r3;
                ldsm_x4t(r0, r1, r2, r3, smem_u32(&sXh[off]));
                bh[p * 2][0] = r0; bh[p * 2][1] = r1;
                bh[p * 2 + 1][0] = r2; bh[p * 2 + 1][1] = r3;
            }
            #pragma unroll
            for (int a = 0; a < 2; a++)
                #pragma unroll
                for (int n = 0; n < 4; n++)
                    mma_bf16(acc[a][n], ah[a], bh[n]);
        }
    }
    int r0 = lane >> 2, c0 = (lane & 3) * 2;
    #pragma unroll
    for (int a = 0; a < 2; a++) {
        int np = wm * 32 + a * 16 + r0;
        #pragma unroll
        for (int n = 0; n < 4; n++) {
            int d = d0 + wn * 32 + n * 8 + c0;
            size_t o0 = (((size_t)seg * BB + b) * NP + np) * DD + d;
            size_t o1 = (((size_t)seg * BB + b) * NP + np + 8) * DD + d;
            *reinterpret_cast<__nv_bfloat162*>(&g_xspb[o0]) =
                __halves2bfloat162(__float2bfloat16_rn(acc[a][n][0]),
                                   __float2bfloat16_rn(acc[a][n][1]));
            *reinterpret_cast<__nv_bfloat162*>(&g_xspb[o1]) =
                __halves2bfloat162(__float2bfloat16_rn(acc[a][n][2]),
                                   __float2bfloat16_rn(acc[a][n][3]));
        }
    }
}

// ===========================================================================
// K6 (mma, cp.async W staging): ys[(b,p)][e] = sum_d xs*W + bias.
#define LDW 264
#define LDK 40
#define YLDWF 264                         // fp32 stage row stride (floats)
#define Y_FST (32 * YLDWF)                // floats per W stage
#define Y_WT (32 * LDW)                   // bf16 elems per W tile
#define Y_AT (16 * LDK)                   // bf16 elems per A tile
__global__ __launch_bounds__(256) void k_ys_mma(const float* __restrict__ W,
                                                const float* __restrict__ bias) {
    extern __shared__ char sm_raw_y[];
    float* sWf = reinterpret_cast<float*>(sm_raw_y);                 // 2 stages fp32
    __nv_bfloat16* sWh = reinterpret_cast<__nv_bfloat16*>(sm_raw_y + 2 * Y_FST * 4); // 2 tiles
    __nv_bfloat16* sAh = sWh + 2 * Y_WT;                             // 2 tiles
    int t = threadIdx.x, lane = t & 31, wid = t >> 5;
    int nexp = blockIdx.y;
    int e0 = blockIdx.x * 256;
    float acc[4][4];
    #pragma unroll
    for (int n = 0; n < 4; n++)
        #pragma unroll
        for (int q = 0; q < 4; q++) acc[n][q] = 0.f;

    int a_row = lane & 15;
    int a_col = (lane >> 4) * 8;
    int aB_row = (lane & 7) + ((lane >> 3) & 1) * 8;
    int aB_col = (lane >> 4) * 8;

    int arow = t >> 3, aq = t & 7;
    int abb = arow >> 1, ap = arow & 1;
    float ainv = 0.f;
    if (t < 128) {
        int npi = nexp * 2 + ap;
        float cs = 0.f;
        #pragma unroll
        for (int i = 0; i < 32; i++)
            cs += g_part[(abb * 32 + i) * NP + npi];
        ainv = 1.0f / cs;
    }
    size_t abase = ((size_t)abb * NP + nexp * 2 + ap) * DD + aq * 4;

    #define Y_LOAD(c, s) do { \
        float* dst = sWf + (s) * Y_FST; \
        _Pragma("unroll") \
        for (int i = 0; i < 8; i++) { \
            int idx = t + i * 256; \
            int row = idx >> 6, q = idx & 63; \
            cp_async16(smem_u32(dst + row * YLDWF + q * 4), \
                       &W[((size_t)nexp * DD + (c) * 32 + row) * DD + e0 + q * 4]); \
        } \
    } while (0)

    Y_LOAD(0, 0);
    CP_COMMIT();
    Y_LOAD(1, 1);
    CP_COMMIT();
    for (int c = 0; c < 32; c++) {
        CP_WAIT1();
        __syncthreads();
        {
            const float* src = sWf + (c & 1) * Y_FST;
            __nv_bfloat16* dst = sWh + (c & 1) * Y_WT;
            #pragma unroll
            for (int i = 0; i < 4; i++) {
                int idx = t + i * 256;
                int row = idx >> 5, q = idx & 31;
                const float* sp = src + row * YLDWF + q * 8;
                float4 v0 = *reinterpret_cast<const float4*>(sp);
                float4 v1 = *reinterpret_cast<const float4*>(sp + 4);
                uint32_t hs[8];
                hs[0] = (uint32_t)__bfloat16_as_ushort(__float2bfloat16_rn(v0.x));
                hs[1] = (uint32_t)__bfloat16_as_ushort(__float2bfloat16_rn(v0.y));
                hs[2] = (uint32_t)__bfloat16_as_ushort(__float2bfloat16_rn(v0.z));
                hs[3] = (uint32_t)__bfloat16_as_ushort(__float2bfloat16_rn(v0.w));
                hs[4] = (uint32_t)__bfloat16_as_ushort(__float2bfloat16_rn(v1.x));
                hs[5] = (uint32_t)__bfloat16_as_ushort(__float2bfloat16_rn(v1.y));
                hs[6] = (uint32_t)__bfloat16_as_ushort(__float2bfloat16_rn(v1.z));
                hs[7] = (uint32_t)__bfloat16_as_ushort(__float2bfloat16_rn(v1.w));
                uint4 hi = {hs[0] | (hs[1] << 16), hs[2] | (hs[3] << 16),
                            hs[4] | (hs[5] << 16), hs[6] | (hs[7] << 16)};
                *reinterpret_cast<uint4*>(&dst[row * LDW + q * 8]) = hi;
            }
        }
        if (t < 128) {
            size_t off = abase + c * 32;
            float s0 = 0.f, s1 = 0.f, s2 = 0.f, s3 = 0.f;
            #pragma unroll
            for (int seg = 0; seg < NSEG; seg++) {
                uint2 pk = *reinterpret_cast<const uint2*>(
                    &g_xspb[(size_t)seg * BB * NP * DD + off]);
                __nv_bfloat162 p0 = *reinterpret_cast<const __nv_bfloat162*>(&pk.x);
                __nv_bfloat162 p1 = *reinterpret_cast<const __nv_bfloat162*>(&pk.y);
                s0 += __bfloat162float(p0.x); s1 += __bfloat162float(p0.y);
                s2 += __bfloat162float(p1.x); s3 += __bfloat162float(p1.y);
            }
            uint32_t h0 = (uint32_t)__bfloat16_as_ushort(__float2bfloat16_rn(s0 * ainv));
            uint32_t h1 = (uint32_t)__bfloat16_as_ushort(__float2bfloat16_rn(s1 * ainv));
            uint32_t h2 = (uint32_t)__bfloat16_as_ushort(__float2bfloat16_rn(s2 * ainv));
            uint32_t h3 = (uint32_t)__bfloat16_as_ushort(__float2bfloat16_rn(s3 * ainv));
            uint2 pk = {h0 | (h1 << 16), h2 | (h3 << 16)};
            *reinterpret_cast<uint2*>(&sAh[(c & 1) * Y_AT + arow * LDK + aq * 4]) = pk;
        }
        __syncthreads();
        if (c + 2 < 32) { Y_LOAD(c + 2, c & 1); }
        CP_COMMIT();
        __nv_bfloat16* tW = sWh + (c & 1) * Y_WT;
        __nv_bfloat16* tA = sAh + (c & 1) * Y_AT;
        #pragma unroll
        for (int ks = 0; ks < 2; ks++) {
            uint32_t ah[4], bh[4][2];
            {
                int off = a_row * LDK + ks * 16 + a_col;
                ldsm_x4(ah[0], ah[1], ah[2], ah[3], smem_u32(&tA[off]));
            }
            #pragma unroll
            for (int p = 0; p < 2; p++) {
                int nb = wid * 32 + p * 16 + aB_col;
                int off = (ks * 16 + aB_row) * LDW + nb;
                uint32_t r0, r1, r2, r3;
                ldsm_x4t(r0, r1, r2, r3, smem_u32(&tW[off]));
                bh[p * 2][0] = r0; bh[p * 2][1] = r1;
                bh[p * 2 + 1][0] = r2; bh[p * 2 + 1][1] = r3;
            }
            #pragma unroll
            for (int n = 0; n < 4; n++)
                mma_bf16(acc[n], ah, bh[n]);
        }
    }
    int r0 = lane >> 2, c0 = (lane & 3) * 2;
    #pragma unroll
    for (int n = 0; n < 4; n++) {
        int e = e0 + wid * 32 + n * 8 + c0;
        float2 bv = *reinterpret_cast<const float2*>(&bias[nexp * DD + e]);
        #pragma unroll
        for (int h = 0; h < 2; h++) {
            int row = r0 + h * 8;
            int bb = row >> 1, p = row & 1;
            float v0 = acc[n][h * 2 + 0] + bv.x;
            float v1 = acc[n][h * 2 + 1] + bv.y;
            size_t o = ((size_t)bb * NP + nexp * 2 + p) * DD + e;
            *reinterpret_cast<__nv_bfloat162*>(&g_ysh[o]) =
                __halves2bfloat162(__float2bfloat16_rn(v0), __float2bfloat16_rn(v1));
        }
    }
}

// ===========================================================================
// K7 (mma, cp.async 3-stage): y[m][d] = rsinv[m]*sum_np E[m][np]*ys[np][d] + x[m][d]
#define CLDA 40
#define C_ASZ (128 * CLDA)
#define C_BSZ (32 * LDE)
#define C_SST (C_ASZ + C_BSZ)
__global__ __launch_bounds__(256) void k_combine_mma(const float* __restrict__ x,
                                                     float* __restrict__ y) {
    extern __shared__ __nv_bfloat16 sm_c[];
    int t = threadIdx.x, lane = t & 31, wid = t >> 5;
    int b = blockIdx.z;
    int tokbase = b * MM + blockIdx.x * 128;
    int d0 = blockIdx.y * 128;
    int wm = wid & 1, wn = wid >> 1;
    float acc[4][4][4];
    #pragma unroll
    for (int a = 0; a < 4; a++)
        #pragma unroll
        for (int n = 0; n < 4; n++)
            #pragma unroll
            for (int q = 0; q < 4; q++) acc[a][n][q] = 0.f;

    int a_row = lane & 15;
    int a_col = (lane >> 4) * 8;
    int aB_row = (lane & 7) + ((lane >> 3) & 1) * 8;
    int aB_col = (lane >> 4) * 8;

    #define C_LOAD(c, s) do { \
        __nv_bfloat16* base = sm_c + (s) * C_SST; \
        _Pragma("unroll") \
        for (int i = 0; i < 2; i++) { \
            int idx = t + i * 256; \
            int row = idx >> 2, q = idx & 3; \
            size_t ge = (size_t)(tokbase + row) * NP + (c) * 32 + q * 8; \
            cp_async16(smem_u32(base + row * CLDA + q * 8), &g_Eh[ge]); \
            int rowb = idx >> 4, qb = idx & 15; \
            size_t gy = ((size_t)b * NP + (c) * 32 + rowb) * DD + d0 + qb * 8; \
            cp_async16(smem_u32(base + C_ASZ + rowb * LDE + qb * 8), &g_ysh[gy]); \
        } \
    } while (0)

    C_LOAD(0, 0);
    CP_COMMIT();
    C_LOAD(1, 1);
    CP_COMMIT();
    for (int c = 0; c < 4; c++) {
        CP_WAIT1();
        __syncthreads();
        if (c + 2 < 4) C_LOAD(c + 2, (c + 2) % 3);
        CP_COMMIT();
        __nv_bfloat16* sAh = sm_c + (c % 3) * C_SST;
        __nv_bfloat16* sBh = sAh + C_ASZ;
        #pragma unroll
        for (int ks = 0; ks < 2; ks++) {
            uint32_t ah[4][4], bh[4][2];
            #pragma unroll
            for (int a = 0; a < 4; a++) {
                int off = (wm * 64 + a * 16 + a_row) * CLDA + ks * 16 + a_col;
                ldsm_x4(ah[a][0], ah[a][1], ah[a][2], ah[a][3], smem_u32(&sAh[off]));
            }
            #pragma unroll
            for (int p = 0; p < 2; p++) {
                int nb = wn * 32 + p * 16 + aB_col;
                int off = (ks * 16 + aB_row) * LDE + nb;
                uint32_t r0, r1, r2, r3;
                ldsm_x4t(r0, r1, r2, r3, smem_u32(&sBh[off]));
                bh[p * 2][0] = r0; bh[p * 2][1] = r1;
                bh[p * 2 + 1][0] = r2; bh[p * 2 + 1][1] = r3;
            }
            #pragma unroll
            for (int a = 0; a < 4; a++)
                #pragma unroll
                for (int n = 0; n < 4; n++)
                    mma_bf16(acc[a][n], ah[a], bh[n]);
        }
    }
    int r0 = lane >> 2, c0 = (lane & 3) * 2;
    #pragma unroll
    for (int a = 0; a < 4; a++) {
        int m0 = tokbase + wm * 64 + a * 16 + r0;
        float rs0 = g_rsinv[m0];
        float rs1 = g_rsinv[m0 + 8];
        #pragma unroll
        for (int n = 0; n < 4; n++) {
            int d = d0 + wn * 32 + n * 8 + c0;
            size_t i0 = (size_t)m0 * DD + d;
            size_t i1 = (size_t)(m0 + 8) * DD + d;
            float2 xv0 = *reinterpret_cast<const float2*>(&x[i0]);
            float2 xv1 = *reinterpret_cast<const float2*>(&x[i1]);
            *reinterpret_cast<float2*>(&y[i0]) =
                make_float2(acc[a][n][0] * rs0 + xv0.x, acc[a][n][1] * rs0 + xv0.y);
            *reinterpret_cast<float2*>(&y[i1]) =
                make_float2(acc[a][n][2] * rs1 + xv1.x, acc[a][n][3] * rs1 + xv1.y);
        }
    }
}

// ---------------------------------------------------------------------------
extern "C" void kernel_launch(void* const* d_in, const int* in_sizes, int n_in,
                              void* d_out, int out_size) {
    const float* x     = (const float*)d_in[0];  // [8,4096,1024]
    const float* phi   = (const float*)d_in[1];  // [1024,64,2]
    const float* scale = (const float*)d_in[2];  // [1]
    const float* W     = (const float*)d_in[3];  // [64,1024,1024]
    const float* bias  = (const float*)d_in[4];  // [64,1024]
    float* y = (float*)d_out;                    // [8,4096,1024]

    const int smem_logits  = 3 * L_SST * 2;                             // 110592
    const int smem_xs      = 3 * X_SST * 2;                             // 104448
    const int smem_ys      = 2 * Y_FST * 4 + 2 * Y_WT * 2 + 2 * Y_AT * 2; // 104448
    const int smem_combine = 3 * C_SST * 2;                             // 56832
    cudaFuncSetAttribute(k_logits_mma, cudaFuncAttributeMaxDynamicSharedMemorySize, smem_logits);
    cudaFuncSetAttribute(k_xs_mma, cudaFuncAttributeMaxDynamicSharedMemorySize, smem_xs);
    cudaFuncSetAttribute(k_ys_mma, cudaFuncAttributeMaxDynamicSharedMemorySize, smem_ys);
    cudaFuncSetAttribute(k_combine_mma, cudaFuncAttributeMaxDynamicSharedMemorySize, smem_combine);

    k_phinorm<<<NP, 256>>>(phi, scale);
    k_rinv<<<BM / 8, 256>>>(x);
    k_logits_mma<<<BM / 128, 512, smem_logits>>>();
    k_xs_mma<<<dim3(8, BB, NSEG), 512, smem_xs>>>();
    k_ys_mma<<<dim3(4, NEXP), 256, smem_ys>>>(W, bias);
    k_combine_mma<<<dim3(32, 8, BB), 256, smem_combine>>>(x, y);
}

// round 17
// speedup vs baseline: 1.0622x; 1.0202x over previous
#include <cuda_runtime.h>
#include <cuda_bf16.h>
#include <math.h>
#include <stdint.h>

// Problem constants
#define BB 8
#define MM 4096
#define DD 1024
#define NEXP 64
#define NP 128            // NEXP * PP
#define BM (BB * MM)      // 32768 tokens
#define NSEG 4            // m-segments for xs reduction
#define SEGM (MM / NSEG)  // 1024
#define LOG2E 1.4426950408889634f

static __device__ __constant__ float c_eps = 1e-12f;

// ---- scratch (device globals; no allocation allowed) ----
__device__ __align__(16) __nv_bfloat16 g_phinth[NP * DD];       // phin^T [np][d]
__device__ __align__(16) __nv_bfloat16 g_xh[(size_t)BM * DD];   // x bf16 [tok][d]
__device__ __align__(16) __nv_bfloat16 g_Eh[(size_t)BM * NP];   // E bf16 [tok][np]
__device__ __align__(16) __nv_bfloat16 g_ysh[BB * NP * DD];     // ys bf16 [b*NP+np][d]
__device__ __align__(16) __nv_bfloat16 g_xspb[(size_t)NSEG * BB * NP * DD]; // bf16 partial slot inputs
__device__ float g_rinv[BM];              // per-token (1/TEMP)/max(||x||,eps)
__device__ float g_part[256 * NP];        // per-mtile column partial sums
__device__ float g_rsinv[BM];             // 1/rowsum (combine denominators)

// ============================ helpers =====================================
__device__ __forceinline__ uint32_t smem_u32(const void* p) {
    uint32_t a;
    asm("{ .reg .u64 t; cvta.to.shared.u64 t, %1; cvt.u32.u64 %0, t; }"
        : "=r"(a) : "l"(p));
    return a;
}
__device__ __forceinline__ void cp_async16(uint32_t saddr, const void* gptr) {
    asm volatile("cp.async.cg.shared.global [%0], [%1], 16;"
                 :: "r"(saddr), "l"(gptr));
}
#define CP_COMMIT() asm volatile("cp.async.commit_group;" ::: "memory")
#define CP_WAIT1()  asm volatile("cp.async.wait_group 1;" ::: "memory")
#define CP_WAIT0()  asm volatile("cp.async.wait_group 0;" ::: "memory")
__device__ __forceinline__ void ldsm_x4(uint32_t& r0, uint32_t& r1, uint32_t& r2,
                                        uint32_t& r3, uint32_t a) {
    asm volatile("ldmatrix.sync.aligned.m8n8.x4.shared.b16 {%0,%1,%2,%3}, [%4];"
                 : "=r"(r0), "=r"(r1), "=r"(r2), "=r"(r3) : "r"(a));
}
__device__ __forceinline__ void ldsm_x4t(uint32_t& r0, uint32_t& r1, uint32_t& r2,
                                         uint32_t& r3, uint32_t a) {
    asm volatile("ldmatrix.sync.aligned.m8n8.x4.trans.shared.b16 {%0,%1,%2,%3}, [%4];"
                 : "=r"(r0), "=r"(r1), "=r"(r2), "=r"(r3) : "r"(a));
}
__device__ __forceinline__ void mma_bf16(float* d, const uint32_t* a, const uint32_t* b) {
    asm volatile(
        "mma.sync.aligned.m16n8k16.row.col.f32.bf16.bf16.f32 "
        "{%0,%1,%2,%3}, {%4,%5,%6,%7}, {%8,%9}, {%0,%1,%2,%3};"
        : "+f"(d[0]), "+f"(d[1]), "+f"(d[2]), "+f"(d[3])
        : "r"(a[0]), "r"(a[1]), "r"(a[2]), "r"(a[3]), "r"(b[0]), "r"(b[1]));
}
__device__ __forceinline__ float ex2f(float x) {
    float r;
    asm("ex2.approx.f32 %0, %1;" : "=f"(r) : "f"(x));
    return r;
}
__device__ __forceinline__ float warpReduceSum(float v) {
    v += __shfl_down_sync(0xffffffffu, v, 16);
    v += __shfl_down_sync(0xffffffffu, v, 8);
    v += __shfl_down_sync(0xffffffffu, v, 4);
    v += __shfl_down_sync(0xffffffffu, v, 2);
    v += __shfl_down_sync(0xffffffffu, v, 1);
    return v;
}

// ===========================================================================
// K1: phin^T bf16
__global__ void k_phinorm(const float* __restrict__ phi, const float* __restrict__ scale) {
    int np = blockIdx.x;
    int t = threadIdx.x;
    float s = 0.f;
    for (int d = t; d < DD; d += 256) {
        float v = phi[d * NP + np];
        s += v * v;
    }
    __shared__ float red[8];
    s = warpReduceSum(s);
    if ((t & 31) == 0) red[t >> 5] = s;
    __syncthreads();
    if (t < 32) {
        float v = (t < 8) ? red[t] : 0.f;
        v = warpReduceSum(v);
        if (t == 0) red[0] = scale[0] / fmaxf(sqrtf(v), c_eps);
    }
    __syncthreads();
    float rn = red[0];
    for (int d = t; d < DD; d += 256)
        g_phinth[np * DD + d] = __float2bfloat16_rn(phi[d * NP + np] * rn);
}

// K2: row norms + x -> bf16. Warp per token.
__global__ void k_rinv(const float* __restrict__ x) {
    int w = threadIdx.x >> 5;
    int lane = threadIdx.x & 31;
    int tok = blockIdx.x * 8 + w;
    const float4* xr = reinterpret_cast<const float4*>(x + (size_t)tok * DD);
    float s = 0.f;
    #pragma unroll
    for (int i = 0; i < 8; i++) {
        float4 v = xr[lane + i * 32];
        s += v.x * v.x + v.y * v.y + v.z * v.z + v.w * v.w;
        __nv_bfloat162 p0 = __halves2bfloat162(__float2bfloat16_rn(v.x), __float2bfloat16_rn(v.y));
        __nv_bfloat162 p1 = __halves2bfloat162(__float2bfloat16_rn(v.z), __float2bfloat16_rn(v.w));
        size_t off = (size_t)tok * DD + (lane + i * 32) * 4;
        *reinterpret_cast<__nv_bfloat162*>(&g_xh[off])     = p0;
        *reinterpret_cast<__nv_bfloat162*>(&g_xh[off + 2]) = p1;
    }
    s = warpReduceSum(s);
    if (lane == 0) g_rinv[tok] = 10.0f / fmaxf(sqrtf(s), c_eps);  // 1/TEMP
}

// ===========================================================================
// K3 (mma, cp.async 3-stage, k-chunk=64): E = exp2((x.phin)*rinv*log2e).
// CTA 128m x 128n, 16 chunks of 64. Fused rowsum + column partials.
#define LDA 72
#define L_AST (128 * LDA)
#define L_SST (2 * L_AST)
__global__ __launch_bounds__(256, 2) void k_logits_mma() {
    extern __shared__ __nv_bfloat16 sm_l[];
    int t = threadIdx.x, lane = t & 31, wid = t >> 5;
    int tok0 = blockIdx.x * 128;
    int wm = wid & 1, wn = wid >> 1;
    float acc[4][4][4];
    #pragma unroll
    for (int a = 0; a < 4; a++)
        #pragma unroll
        for (int n = 0; n < 4; n++)
            #pragma unroll
            for (int q = 0; q < 4; q++) acc[a][n][q] = 0.f;

    int a_row = lane & 15;
    int a_col = (lane >> 4) * 8;
    int b_row = (lane & 7) + ((lane >> 4) << 3);
    int b_col = ((lane >> 3) & 1) * 8;

    #define L_LOAD(c, s) do { \
        __nv_bfloat16* base = sm_l + (s) * L_SST; \
        _Pragma("unroll") \
        for (int i = 0; i < 4; i++) { \
            int idx = t + i * 256; \
            int row = idx >> 3, q = idx & 7; \
            size_t ga = (size_t)(tok0 + row) * DD + (c) * 64 + q * 8; \
            size_t gb = (size_t)row * DD + (c) * 64 + q * 8; \
            int so = row * LDA + q * 8; \
            cp_async16(smem_u32(base + so), &g_xh[ga]); \
            cp_async16(smem_u32(base + L_AST + so), &g_phinth[gb]); \
        } \
    } while (0)

    L_LOAD(0, 0); CP_COMMIT();
    L_LOAD(1, 1); CP_COMMIT();
    for (int c = 0; c < 16; c++) {
        CP_WAIT1();
        __syncthreads();
        if (c + 2 < 16) L_LOAD(c + 2, (c + 2) % 3);
        CP_COMMIT();
        __nv_bfloat16* sAh = sm_l + (c % 3) * L_SST;
        __nv_bfloat16* sBh = sAh + L_AST;
        #pragma unroll
        for (int ks = 0; ks < 4; ks++) {
            uint32_t ah[4][4], bh[4][2];
            #pragma unroll
            for (int a = 0; a < 4; a++) {
                int off = (wm * 64 + a * 16 + a_row) * LDA + ks * 16 + a_col;
                ldsm_x4(ah[a][0], ah[a][1], ah[a][2], ah[a][3], smem_u32(&sAh[off]));
            }
            #pragma unroll
            for (int p = 0; p < 2; p++) {
                int off = (wn * 32 + p * 16 + b_row) * LDA + ks * 16 + b_col;
                uint32_t r0, r1, r2, r3;
                ldsm_x4(r0, r1, r2, r3, smem_u32(&sBh[off]));
                bh[p * 2][0] = r0; bh[p * 2][1] = r1;
                bh[p * 2 + 1][0] = r2; bh[p * 2 + 1][1] = r3;
            }
            #pragma unroll
            for (int a = 0; a < 4; a++)
                #pragma unroll
                for (int n = 0; n < 4; n++)
                    mma_bf16(acc[a][n], ah[a], bh[n]);
        }
    }
    // epilogue: exp2, store bf16; accumulate row/col sums (fp32, pre-rounding)
    int r0 = lane >> 2, c0 = (lane & 3) * 2;
    float rsum[4][2];
    float csum[4][2];
    #pragma unroll
    for (int a = 0; a < 4; a++) { rsum[a][0] = 0.f; rsum[a][1] = 0.f; }
    #pragma unroll
    for (int n = 0; n < 4; n++) { csum[n][0] = 0.f; csum[n][1] = 0.f; }
    __syncthreads();
    #pragma unroll
    for (int a = 0; a < 4; a++) {
        int row = tok0 + wm * 64 + a * 16 + r0;
        float rv0 = g_rinv[row] * LOG2E;
        float rv1 = g_rinv[row + 8] * LOG2E;
        #pragma unroll
        for (int n = 0; n < 4; n++) {
            int col = wn * 32 + n * 8 + c0;
            float e0 = ex2f(acc[a][n][0] * rv0), e1 = ex2f(acc[a][n][1] * rv0);
            float e2 = ex2f(acc[a][n][2] * rv1), e3 = ex2f(acc[a][n][3] * rv1);
            rsum[a][0] += e0 + e1;
            rsum[a][1] += e2 + e3;
            csum[n][0] += e0 + e2;
            csum[n][1] += e1 + e3;
            *reinterpret_cast<__nv_bfloat162*>(&g_Eh[(size_t)row * NP + col]) =
                __halves2bfloat162(__float2bfloat16_rn(e0), __float2bfloat16_rn(e1));
            *reinterpret_cast<__nv_bfloat162*>(&g_Eh[(size_t)(row + 8) * NP + col]) =
                __halves2bfloat162(__float2bfloat16_rn(e2), __float2bfloat16_rn(e3));
        }
    }
    float* srow = reinterpret_cast<float*>(sm_l);   // [4 wn][128 rows]
    float* scol = srow + 4 * 128;                   // [2 wm][128 cols]
    __syncthreads();
    #pragma unroll
    for (int a = 0; a < 4; a++)
        #pragma unroll
        for (int h = 0; h < 2; h++) {
            float v = rsum[a][h];
            v += __shfl_xor_sync(0xffffffffu, v, 1);
            v += __shfl_xor_sync(0xffffffffu, v, 2);
            if ((lane & 3) == 0)
                srow[wn * 128 + wm * 64 + a * 16 + h * 8 + r0] = v;
        }
    #pragma unroll
    for (int n = 0; n < 4; n++)
        #pragma unroll
        for (int q1 = 0; q1 < 2; q1++) {
            float v = csum[n][q1];
            v += __shfl_xor_sync(0xffffffffu, v, 4);
            v += __shfl_xor_sync(0xffffffffu, v, 8);
            v += __shfl_xor_sync(0xffffffffu, v, 16);
            if (lane < 4)
                scol[wm * 128 + wn * 32 + n * 8 + lane * 2 + q1] = v;
        }
    __syncthreads();
    if (t < 128) {
        float rs = srow[t] + srow[128 + t] + srow[256 + t] + srow[384 + t];
        g_rsinv[tok0 + t] = 1.0f / rs;
        g_part[blockIdx.x * NP + t] = scol[t] + scol[128 + t];
    }
}

// ===========================================================================
// K5 (mma, cp.async 3-stage, k-chunk=64, NSEG=4 m-segments):
// xspb[seg][b][np][d] = sum_{m in seg} E[m][np]*x[m][d].  CTA 128np x 128d.
#define LDE 136
#define X_AST (64 * LDE)
#define X_SST (2 * X_AST)
__global__ __launch_bounds__(256, 2) void k_xs_mma() {
    extern __shared__ __nv_bfloat16 sm_x[];
    int t = threadIdx.x, lane = t & 31, wid = t >> 5;
    int d0 = blockIdx.x * 128;
    int b = blockIdx.y;
    int seg = blockIdx.z;
    int base = b * MM + seg * SEGM;
    int wm = wid & 1, wn = wid >> 1;
    float acc[4][4][4];
    #pragma unroll
    for (int a = 0; a < 4; a++)
        #pragma unroll
        for (int n = 0; n < 4; n++)
            #pragma unroll
            for (int q = 0; q < 4; q++) acc[a][n][q] = 0.f;

    int aA_col = ((lane >> 3) & 1) * 8;
    int aA_row = (lane & 7) + (lane >> 4) * 8;
    int aB_row = (lane & 7) + ((lane >> 3) & 1) * 8;
    int aB_col = (lane >> 4) * 8;

    #define X_LOAD(c, s) do { \
        __nv_bfloat16* bb_ = sm_x + (s) * X_SST; \
        _Pragma("unroll") \
        for (int i = 0; i < 4; i++) { \
            int idx = t + i * 256; \
            int row = idx >> 4, q = idx & 15; \
            size_t ge = (size_t)(base + (c) * 64 + row) * NP + q * 8; \
            size_t gx = (size_t)(base + (c) * 64 + row) * DD + d0 + q * 8; \
            int so = row * LDE + q * 8; \
            cp_async16(smem_u32(bb_ + so), &g_Eh[ge]); \
            cp_async16(smem_u32(bb_ + X_AST + so), &g_xh[gx]); \
        } \
    } while (0)

    X_LOAD(0, 0); CP_COMMIT();
    X_LOAD(1, 1); CP_COMMIT();
    for (int c = 0; c < SEGM / 64; c++) {
        CP_WAIT1();
        __syncthreads();
        if (c + 2 < SEGM / 64) X_LOAD(c + 2, (c + 2) % 3);
        CP_COMMIT();
        __nv_bfloat16* sEh = sm_x + (c % 3) * X_SST;
        __nv_bfloat16* sXh = sEh + X_AST;
        #pragma unroll
        for (int ks = 0; ks < 4; ks++) {
            uint32_t ah[4][4], bh[4][2];
            #pragma unroll
            for (int a = 0; a < 4; a++) {
                int npb = wm * 64 + a * 16 + aA_col;
                int off = (ks * 16 + aA_row) * LDE + npb;
                ldsm_x4t(ah[a][0], ah[a][1], ah[a][2], ah[a][3], smem_u32(&sEh[off]));
            }
            #pragma unroll
            for (int p = 0; p < 2; p++) {
                int nb = wn * 32 + p * 16 + aB_col;
                int off = (ks * 16 + aB_row) * LDE + nb;
                uint32_t r0, r1, r2, r3;
                ldsm_x4t(r0, r1, r2, r3, smem_u32(&sXh[off]));
                bh[p * 2][0] = r0; bh[p * 2][1] = r1;
                bh[p * 2 + 1][0] = r2; bh[p * 2 + 1][1] = r3;
            }
            #pragma unroll
            for (int a = 0; a < 4; a++)
                #pragma unroll
                for (int n = 0; n < 4; n++)
                    mma_bf16(acc[a][n], ah[a], bh[n]);
        }
    }
    int r0 = lane >> 2, c0 = (lane & 3) * 2;
    #pragma unroll
    for (int a = 0; a < 4; a++) {
        int np = wm * 64 + a * 16 + r0;
        #pragma unroll
        for (int n = 0; n < 4; n++) {
            int d = d0 + wn * 32 + n * 8 + c0;
            size_t o0 = (((size_t)seg * BB + b) * NP + np) * DD + d;
            size_t o1 = (((size_t)seg * BB + b) * NP + np + 8) * DD + d;
            *reinterpret_cast<__nv_bfloat162*>(&g_xspb[o0]) =
                __halves2bfloat162(__float2bfloat16_rn(acc[a][n][0]),
                                   __float2bfloat16_rn(acc[a][n][1]));
            *reinterpret_cast<__nv_bfloat162*>(&g_xspb[o1]) =
                __halves2bfloat162(__float2bfloat16_rn(acc[a][n][2]),
                                   __float2bfloat16_rn(acc[a][n][3]));
        }
    }
}

// ===========================================================================
// K6 (mma, cp.async W staging): ys[(b,p)][e] = sum_d xs*W + bias.
#define LDW 264
#define LDK 40
#define YLDWF 264                         // fp32 stage row stride (floats)
#define Y_FST (32 * YLDWF)                // floats per W stage
#define Y_WT (32 * LDW)                   // bf16 elems per W tile
#define Y_AT (16 * LDK)                   // bf16 elems per A tile
__global__ __launch_bounds__(256) void k_ys_mma(const float* __restrict__ W,
                                                const float* __restrict__ bias) {
    extern __shared__ char sm_raw_y[];
    float* sWf = reinterpret_cast<float*>(sm_raw_y);                 // 2 stages fp32
    __nv_bfloat16* sWh = reinterpret_cast<__nv_bfloat16*>(sm_raw_y + 2 * Y_FST * 4); // 2 tiles
    __nv_bfloat16* sAh = sWh + 2 * Y_WT;                             // 2 tiles
    int t = threadIdx.x, lane = t & 31, wid = t >> 5;
    int nexp = blockIdx.y;
    int e0 = blockIdx.x * 256;
    float acc[4][4];
    #pragma unroll
    for (int n = 0; n < 4; n++)
        #pragma unroll
        for (int q = 0; q < 4; q++) acc[n][q] = 0.f;

    int a_row = lane & 15;
    int a_col = (lane >> 4) * 8;
    int aB_row = (lane & 7) + ((lane >> 3) & 1) * 8;
    int aB_col = (lane >> 4) * 8;

    int arow = t >> 3, aq = t & 7;
    int abb = arow >> 1, ap = arow & 1;
    float ainv = 0.f;
    if (t < 128) {
        int npi = nexp * 2 + ap;
        float cs = 0.f;
        #pragma unroll
        for (int i = 0; i < 32; i++)
            cs += g_part[(abb * 32 + i) * NP + npi];
        ainv = 1.0f / cs;
    }
    size_t abase = ((size_t)abb * NP + nexp * 2 + ap) * DD + aq * 4;

    #define Y_LOAD(c, s) do { \
        float* dst = sWf + (s) * Y_FST; \
        _Pragma("unroll") \
        for (int i = 0; i < 8; i++) { \
            int idx = t + i * 256; \
            int row = idx >> 6, q = idx & 63; \
            cp_async16(smem_u32(dst + row * YLDWF + q * 4), \
                       &W[((size_t)nexp * DD + (c) * 32 + row) * DD + e0 + q * 4]); \
        } \
    } while (0)

    Y_LOAD(0, 0);
    CP_COMMIT();
    Y_LOAD(1, 1);
    CP_COMMIT();
    for (int c = 0; c < 32; c++) {
        CP_WAIT1();
        __syncthreads();
        {
            const float* src = sWf + (c & 1) * Y_FST;
            __nv_bfloat16* dst = sWh + (c & 1) * Y_WT;
            #pragma unroll
            for (int i = 0; i < 4; i++) {
                int idx = t + i * 256;
                int row = idx >> 5, q = idx & 31;
                const float* sp = src + row * YLDWF + q * 8;
                float4 v0 = *reinterpret_cast<const float4*>(sp);
                float4 v1 = *reinterpret_cast<const float4*>(sp + 4);
                uint32_t hs[8];
                hs[0] = (uint32_t)__bfloat16_as_ushort(__float2bfloat16_rn(v0.x));
                hs[1] = (uint32_t)__bfloat16_as_ushort(__float2bfloat16_rn(v0.y));
                hs[2] = (uint32_t)__bfloat16_as_ushort(__float2bfloat16_rn(v0.z));
                hs[3] = (uint32_t)__bfloat16_as_ushort(__float2bfloat16_rn(v0.w));
                hs[4] = (uint32_t)__bfloat16_as_ushort(__float2bfloat16_rn(v1.x));
                hs[5] = (uint32_t)__bfloat16_as_ushort(__float2bfloat16_rn(v1.y));
                hs[6] = (uint32_t)__bfloat16_as_ushort(__float2bfloat16_rn(v1.z));
                hs[7] = (uint32_t)__bfloat16_as_ushort(__float2bfloat16_rn(v1.w));
                uint4 hi = {hs[0] | (hs[1] << 16), hs[2] | (hs[3] << 16),
                            hs[4] | (hs[5] << 16), hs[6] | (hs[7] << 16)};
                *reinterpret_cast<uint4*>(&dst[row * LDW + q * 8]) = hi;
            }
        }
        if (t < 128) {
            size_t off = abase + c * 32;
            float s0 = 0.f, s1 = 0.f, s2 = 0.f, s3 = 0.f;
            #pragma unroll
            for (int seg = 0; seg < NSEG; seg++) {
                uint2 pk = *reinterpret_cast<const uint2*>(
                    &g_xspb[(size_t)seg * BB * NP * DD + off]);
                __nv_bfloat162 p0 = *reinterpret_cast<const __nv_bfloat162*>(&pk.x);
                __nv_bfloat162 p1 = *reinterpret_cast<const __nv_bfloat162*>(&pk.y);
                s0 += __bfloat162float(p0.x); s1 += __bfloat162float(p0.y);
                s2 += __bfloat162float(p1.x); s3 += __bfloat162float(p1.y);
            }
            uint32_t h0 = (uint32_t)__bfloat16_as_ushort(__float2bfloat16_rn(s0 * ainv));
            uint32_t h1 = (uint32_t)__bfloat16_as_ushort(__float2bfloat16_rn(s1 * ainv));
            uint32_t h2 = (uint32_t)__bfloat16_as_ushort(__float2bfloat16_rn(s2 * ainv));
            uint32_t h3 = (uint32_t)__bfloat16_as_ushort(__float2bfloat16_rn(s3 * ainv));
            uint2 pk = {h0 | (h1 << 16), h2 | (h3 << 16)};
            *reinterpret_cast<uint2*>(&sAh[(c & 1) * Y_AT + arow * LDK + aq * 4]) = pk;
        }
        __syncthreads();
        if (c + 2 < 32) { Y_LOAD(c + 2, c & 1); }
        CP_COMMIT();
        __nv_bfloat16* tW = sWh + (c & 1) * Y_WT;
        __nv_bfloat16* tA = sAh + (c & 1) * Y_AT;
        #pragma unroll
        for (int ks = 0; ks < 2; ks++) {
            uint32_t ah[4], bh[4][2];
            {
                int off = a_row * LDK + ks * 16 + a_col;
                ldsm_x4(ah[0], ah[1], ah[2], ah[3], smem_u32(&tA[off]));
            }
            #pragma unroll
            for (int p = 0; p < 2; p++) {
                int nb = wid * 32 + p * 16 + aB_col;
                int off = (ks * 16 + aB_row) * LDW + nb;
                uint32_t r0, r1, r2, r3;
                ldsm_x4t(r0, r1, r2, r3, smem_u32(&tW[off]));
                bh[p * 2][0] = r0; bh[p * 2][1] = r1;
                bh[p * 2 + 1][0] = r2; bh[p * 2 + 1][1] = r3;
            }
            #pragma unroll
            for (int n = 0; n < 4; n++)
                mma_bf16(acc[n], ah, bh[n]);
        }
    }
    int r0 = lane >> 2, c0 = (lane & 3) * 2;
    #pragma unroll
    for (int n = 0; n < 4; n++) {
        int e = e0 + wid * 32 + n * 8 + c0;
        float2 bv = *reinterpret_cast<const float2*>(&bias[nexp * DD + e]);
        #pragma unroll
        for (int h = 0; h < 2; h++) {
            int row = r0 + h * 8;
            int bb = row >> 1, p = row & 1;
            float v0 = acc[n][h * 2 + 0] + bv.x;
            float v1 = acc[n][h * 2 + 1] + bv.y;
            size_t o = ((size_t)bb * NP + nexp * 2 + p) * DD + e;
            *reinterpret_cast<__nv_bfloat162*>(&g_ysh[o]) =
                __halves2bfloat162(__float2bfloat16_rn(v0), __float2bfloat16_rn(v1));
        }
    }
}

// ===========================================================================
// K7 (mma, k-chunk=64, 2 chunks fully prefetched):
// y[m][d] = rsinv[m]*sum_np E[m][np]*ys[np][d] + x[m][d]
#define CLDA 72
#define C_ASZ (128 * CLDA)
#define C_BSZ (64 * LDE)
#define C_SST (C_ASZ + C_BSZ)
__global__ __launch_bounds__(256, 2) void k_combine_mma(const float* __restrict__ x,
                                                        float* __restrict__ y) {
    extern __shared__ __nv_bfloat16 sm_c[];
    int t = threadIdx.x, lane = t & 31, wid = t >> 5;
    int b = blockIdx.z;
    int tokbase = b * MM + blockIdx.x * 128;
    int d0 = blockIdx.y * 128;
    int wm = wid & 1, wn = wid >> 1;
    float acc[4][4][4];
    #pragma unroll
    for (int a = 0; a < 4; a++)
        #pragma unroll
        for (int n = 0; n < 4; n++)
            #pragma unroll
            for (int q = 0; q < 4; q++) acc[a][n][q] = 0.f;

    int a_row = lane & 15;
    int a_col = (lane >> 4) * 8;
    int aB_row = (lane & 7) + ((lane >> 3) & 1) * 8;
    int aB_col = (lane >> 4) * 8;

    #define C_LOAD(c, s) do { \
        __nv_bfloat16* base = sm_c + (s) * C_SST; \
        _Pragma("unroll") \
        for (int i = 0; i < 4; i++) { \
            int idx = t + i * 256; \
            int row = idx >> 3, q = idx & 7; \
            size_t ge = (size_t)(tokbase + row) * NP + (c) * 64 + q * 8; \
            cp_async16(smem_u32(base + row * CLDA + q * 8), &g_Eh[ge]); \
            int rowb = idx >> 4, qb = idx & 15; \
            size_t gy = ((size_t)b * NP + (c) * 64 + rowb) * DD + d0 + qb * 8; \
            cp_async16(smem_u32(base + C_ASZ + rowb * LDE + qb * 8), &g_ysh[gy]); \
        } \
    } while (0)

    C_LOAD(0, 0);
    CP_COMMIT();
    C_LOAD(1, 1);
    CP_COMMIT();
    #pragma unroll
    for (int c = 0; c < 2; c++) {
        if (c == 0) { CP_WAIT1(); } else { CP_WAIT0(); }
        __syncthreads();
        __nv_bfloat16* sAh = sm_c + c * C_SST;
        __nv_bfloat16* sBh = sAh + C_ASZ;
        #pragma unroll
        for (int ks = 0; ks < 4; ks++) {
            uint32_t ah[4][4], bh[4][2];
            #pragma unroll
            for (int a = 0; a < 4; a++) {
                int off = (wm * 64 + a * 16 + a_row) * CLDA + ks * 16 + a_col;
                ldsm_x4(ah[a][0], ah[a][1], ah[a][2], ah[a][3], smem_u32(&sAh[off]));
            }
            #pragma unroll
            for (int p = 0; p < 2; p++) {
                int nb = wn * 32 + p * 16 + aB_col;
                int off = (ks * 16 + aB_row) * LDE + nb;
                uint32_t r0, r1, r2, r3;
                ldsm_x4t(r0, r1, r2, r3, smem_u32(&sBh[off]));
                bh[p * 2][0] = r0; bh[p * 2][1] = r1;
                bh[p * 2 + 1][0] = r2; bh[p * 2 + 1][1] = r3;
            }
            #pragma unroll
            for (int a = 0; a < 4; a++)
                #pragma unroll
                for (int n = 0; n < 4; n++)
                    mma_bf16(acc[a][n], ah[a], bh[n]);
        }
    }
    int r0 = lane >> 2, c0 = (lane & 3) * 2;
    #pragma unroll
    for (int a = 0; a < 4; a++) {
        int m0 = tokbase + wm * 64 + a * 16 + r0;
        float rs0 = g_rsinv[m0];
        float rs1 = g_rsinv[m0 + 8];
        #pragma unroll
        for (int n = 0; n < 4; n++) {
            int d = d0 + wn * 32 + n * 8 + c0;
            size_t i0 = (size_t)m0 * DD + d;
            size_t i1 = (size_t)(m0 + 8) * DD + d;
            float2 xv0 = *reinterpret_cast<const float2*>(&x[i0]);
            float2 xv1 = *reinterpret_cast<const float2*>(&x[i1]);
            *reinterpret_cast<float2*>(&y[i0]) =
                make_float2(acc[a][n][0] * rs0 + xv0.x, acc[a][n][1] * rs0 + xv0.y);
            *reinterpret_cast<float2*>(&y[i1]) =
                make_float2(acc[a][n][2] * rs1 + xv1.x, acc[a][n][3] * rs1 + xv1.y);
        }
    }
}

// ---------------------------------------------------------------------------
extern "C" void kernel_launch(void* const* d_in, const int* in_sizes, int n_in,
                              void* d_out, int out_size) {
    const float* x     = (const float*)d_in[0];  // [8,4096,1024]
    const float* phi   = (const float*)d_in[1];  // [1024,64,2]
    const float* scale = (const float*)d_in[2];  // [1]
    const float* W     = (const float*)d_in[3];  // [64,1024,1024]
    const float* bias  = (const float*)d_in[4];  // [64,1024]
    float* y = (float*)d_out;                    // [8,4096,1024]

    const int smem_logits  = 3 * L_SST * 2;                             // 110592
    const int smem_xs      = 3 * X_SST * 2;                             // 104448
    const int smem_ys      = 2 * Y_FST * 4 + 2 * Y_WT * 2 + 2 * Y_AT * 2; // 104448
    const int smem_combine = 2 * C_SST * 2;                             // 71680
    cudaFuncSetAttribute(k_logits_mma, cudaFuncAttributeMaxDynamicSharedMemorySize, smem_logits);
    cudaFuncSetAttribute(k_xs_mma, cudaFuncAttributeMaxDynamicSharedMemorySize, smem_xs);
    cudaFuncSetAttribute(k_ys_mma, cudaFuncAttributeMaxDynamicSharedMemorySize, smem_ys);
    cudaFuncSetAttribute(k_combine_mma, cudaFuncAttributeMaxDynamicSharedMemorySize, smem_combine);

    k_phinorm<<<NP, 256>>>(phi, scale);
    k_rinv<<<BM / 8, 256>>>(x);
    k_logits_mma<<<BM / 128, 256, smem_logits>>>();
    k_xs_mma<<<dim3(8, BB, NSEG), 256, smem_xs>>>();
    k_ys_mma<<<dim3(4, NEXP), 256, smem_ys>>>(W, bias);
    k_combine_mma<<<dim3(32, 8, BB), 256, smem_combine>>>(x, y);
}